// round 1
// baseline (speedup 1.0000x reference)
#include <cuda_runtime.h>
#include <math.h>

// Problem constants (fixed by the reference's setup)
#define N_IN 1000000
#define M_NODES 2000000
#define S0 (2 * N_IN + 2)

// Scratch (no cudaMalloc allowed): encoded input + two ping-pong M-buffers
__device__ float g_enc[S0];
__device__ float g_bufA[M_NODES];
__device__ float g_bufB[M_NODES];

// log(1 - exp(x)) for x <= 0, stable (Maechler 2012), matching reference
__device__ __forceinline__ float log1mexp_f(float x) {
    const float NLOG2 = -0.69314718056f;
    if (x > NLOG2) {
        return logf(-expm1f(x));     // x in (-log2, 0]; x=0 -> log(0) = -inf
    } else {
        return log1pf(-expf(x));
    }
}

__global__ void encode_kernel(const float* __restrict__ pos) {
    int i = blockIdx.x * blockDim.x + threadIdx.x;
    if (i == 0) {
        g_enc[0] = -INFINITY;  // literal False
        g_enc[1] = 0.0f;       // literal True
    }
    if (i < N_IN) {
        float p = pos[i];
        g_enc[2 + 2 * i] = p;
        g_enc[3 + 2 * i] = log1mexp_f(p);
    }
}

// product layer: out[m] = sum of 4 gathered log-probs
__global__ void product_kernel(const float* __restrict__ src,
                               const int4* __restrict__ ptrs,
                               float* __restrict__ dst) {
    int m = blockIdx.x * blockDim.x + threadIdx.x;
    if (m >= M_NODES) return;
    int4 p = ptrs[m];
    float a = __ldg(src + p.x);
    float b = __ldg(src + p.y);
    float c = __ldg(src + p.z);
    float d = __ldg(src + p.w);
    dst[m] = (a + b) + (c + d);
}

// sum layer: 4-way logsumexp with 1e-15 floor, max detached.
// If max == -inf (all four gathered are -inf), reference's nan_to_num path
// yields log(eps) + (-inf) = -inf.
__global__ void sum_kernel(const float* __restrict__ src,
                           const int4* __restrict__ ptrs,
                           float* __restrict__ dst) {
    int m = blockIdx.x * blockDim.x + threadIdx.x;
    if (m >= M_NODES) return;
    int4 p = ptrs[m];
    float a = __ldg(src + p.x);
    float b = __ldg(src + p.y);
    float c = __ldg(src + p.z);
    float d = __ldg(src + p.w);
    float mx = fmaxf(fmaxf(a, b), fmaxf(c, d));
    float out;
    if (mx == -INFINITY) {
        out = -INFINITY;
    } else {
        float s = expf(a - mx) + expf(b - mx) + expf(c - mx) + expf(d - mx);
        out = logf(s + 1e-15f) + mx;
    }
    dst[m] = out;
}

extern "C" void kernel_launch(void* const* d_in, const int* in_sizes, int n_in,
                              void* d_out, int out_size) {
    const float* pos   = (const float*)d_in[0];
    const int4*  ptrs0 = (const int4*)d_in[1];
    const int4*  ptrs1 = (const int4*)d_in[2];
    const int4*  ptrs2 = (const int4*)d_in[3];
    const int4*  ptrs3 = (const int4*)d_in[4];
    // d_in[5] is csr = repeat(arange(M),4): implicit in our layout (4 consecutive
    // edges per node), so it is not needed.
    float* out = (float*)d_out;

    float* enc;  cudaGetSymbolAddress((void**)&enc,  g_enc);
    float* bufA; cudaGetSymbolAddress((void**)&bufA, g_bufA);
    float* bufB; cudaGetSymbolAddress((void**)&bufB, g_bufB);

    const int T = 256;
    const int blocksEnc = (N_IN + T - 1) / T;
    const int blocksM   = (M_NODES + T - 1) / T;

    encode_kernel<<<blocksEnc, T>>>(pos);
    product_kernel<<<blocksM, T>>>(enc,  ptrs0, bufA);   // product layer 1
    sum_kernel    <<<blocksM, T>>>(bufA, ptrs1, bufB);   // sum layer 1
    product_kernel<<<blocksM, T>>>(bufB, ptrs2, bufA);   // product layer 2
    sum_kernel    <<<blocksM, T>>>(bufA, ptrs3, out);    // sum layer 2
}